// round 10
// baseline (speedup 1.0000x reference)
#include <cuda_runtime.h>

// Fixed dataset geometry: 512x512 grid mesh, batch 32.
#define W 512
#define H 512
#define NV (H * W)
#define FC (W * 3)          // 1536 float columns per grid row
#define FCG 12              // warp covers 128 float-cols (32 float4s)
#define RPW 8               // rows per warp chunk (small + static => deep load batching)
#define CHUNKS (H / RPW)    // 64
#define WPB (FCG * CHUNKS)  // warps per batch = 768
#define BLOCK_THREADS 256
#define WARPS_PER_BLOCK (BLOCK_THREADS / 32)

__global__ void zero_out_kernel(float* out) {
    if (threadIdx.x == 0) out[0] = 0.0f;
}

// MODE: 0 = chunk contains grid row 0, 1 = interior chunk, 2 = chunk contains row H-1.
// EDGE: warp's column group touches the grid's left/right boundary.
template<bool EDGE, int MODE>
__device__ __forceinline__ float walk(const float* __restrict__ vb,
                                      int fidx, int lane, int fbase,
                                      bool doL, bool doR, int r0)
{
    const unsigned FULL = 0xFFFFFFFFu;

    // Edge-only per-column masks / coefficients.
    float mL[4], mR[4], cMid[4], cTop[4], cBot[4];
    if (EDGE) {
#pragma unroll
        for (int t = 0; t < 4; t++) {
            int f = fbase + t;
            mL[t] = (f >= 3)     ? 1.0f : 0.0f;
            mR[t] = (f < FC - 3) ? 1.0f : 0.0f;
            cMid[t] = -1.0f / (2.0f + 2.0f * (mL[t] + mR[t]));
            cTop[t] = -1.0f / (1.0f + 2.0f * mL[t] + mR[t]);
            cBot[t] = -1.0f / (1.0f + mL[t] + 2.0f * mR[t]);
        }
    }

    // Row state: a = i-1, b = i, c = i+1; *m3/*p3 = shifted by -3/+3 floats.
    float4 a4, b4, c4;
    float ap3[3], bm3[3], bp3[3], cm3[3], cp3[3];
    float acc = 0.0f;

    auto load_row = [&](int r, float4& v4, float m3[3], float p3[3]) {
        const float4* rowp = (const float4*)(vb + (size_t)r * FC);
        v4 = __ldg(rowp + fidx);
        float4 hl = make_float4(0.f, 0.f, 0.f, 0.f);
        float4 hr = make_float4(0.f, 0.f, 0.f, 0.f);
        if (doL) hl = __ldg(rowp + fidx - 1);
        if (doR) hr = __ldg(rowp + fidx + 1);
        float uy = __shfl_up_sync(FULL, v4.y, 1);
        float uz = __shfl_up_sync(FULL, v4.z, 1);
        float uw = __shfl_up_sync(FULL, v4.w, 1);
        float dx = __shfl_down_sync(FULL, v4.x, 1);
        float dy = __shfl_down_sync(FULL, v4.y, 1);
        float dz = __shfl_down_sync(FULL, v4.z, 1);
        m3[0] = (lane == 0)  ? hl.y : uy;
        m3[1] = (lane == 0)  ? hl.z : uz;
        m3[2] = (lane == 0)  ? hl.w : uw;
        p3[0] = (lane == 31) ? hr.x : dx;
        p3[1] = (lane == 31) ? hr.y : dy;
        p3[2] = (lane == 31) ? hr.z : dz;
    };

    // phase: 0 = top row (mU=0), 1 = interior, 2 = bottom row (mD=0)
    auto compute = [&](int phase) {
        float bm[4] = {bm3[0], bm3[1], bm3[2], b4.x};
        float bp[4] = {b4.w,  bp3[0], bp3[1], bp3[2]};
        float ap[4] = {a4.w,  ap3[0], ap3[1], ap3[2]};
        float cm[4] = {cm3[0], cm3[1], cm3[2], c4.x};
        float av[4] = {a4.x, a4.y, a4.z, a4.w};
        float cv[4] = {c4.x, c4.y, c4.z, c4.w};
        float bv[4] = {b4.x, b4.y, b4.z, b4.w};
        float mU = (phase == 0) ? 0.0f : 1.0f;
        float mD = (phase == 2) ? 0.0f : 1.0f;
#pragma unroll
        for (int t = 0; t < 4; t++) {
            float Lv;
            if (EDGE) {
                float sl = fmaf(mD, cm[t], bm[t]);
                float sr = fmaf(mU, ap[t], bp[t]);
                float s  = fmaf(mU, av[t], mD * cv[t]);
                s = fmaf(mL[t], sl, s);
                s = fmaf(mR[t], sr, s);
                float coef = (phase == 0) ? cTop[t] : ((phase == 2) ? cBot[t] : cMid[t]);
                Lv = fmaf(coef, s, bv[t]);
            } else {
                float s;
                float coef;
                if (phase == 0) {        // left, right, down, down-left
                    s = (bm[t] + cm[t]) + (bp[t] + cv[t]);
                    coef = -(1.0f / 4.0f);
                } else if (phase == 2) { // left, right, up, up-right
                    s = (bm[t] + bp[t]) + (av[t] + ap[t]);
                    coef = -(1.0f / 4.0f);
                } else {                 // 6 neighbors
                    s = (bm[t] + cm[t]) + ((bp[t] + ap[t]) + (av[t] + cv[t]));
                    coef = -(1.0f / 6.0f);
                }
                Lv = fmaf(coef, s, bv[t]);
            }
            acc = fmaf(Lv, Lv, acc);
        }
    };

    auto rotate = [&]() {
        a4 = b4; b4 = c4;
#pragma unroll
        for (int t = 0; t < 3; t++) { ap3[t] = bp3[t]; bm3[t] = cm3[t]; bp3[t] = cp3[t]; }
    };

    if (MODE == 0) {
        // Chunk rows 0..RPW-1. Peel row 0 (no up-neighbors), then RPW-1 interior rows.
        float dm[3];
        load_row(0, b4, bm3, bp3);
        load_row(1, c4, cm3, cp3);
        // a-state unused for the top row (masked); init to b to keep values finite.
        a4 = b4; ap3[0] = bp3[0]; ap3[1] = bp3[1]; ap3[2] = bp3[2];
        (void)dm;
        compute(0);
        rotate();
#pragma unroll
        for (int k = 0; k < RPW - 1; k++) {       // rows 1..RPW-1, c = rows 2..RPW
            load_row(2 + k, c4, cm3, cp3);
            compute(1);
            rotate();
        }
    } else if (MODE == 1) {
        // Interior chunk: rows r0..r0+RPW-1, all 6-neighbor interior rows.
        float dm[3];
        load_row(r0 - 1, a4, dm, ap3);
        load_row(r0,     b4, bm3, bp3);
#pragma unroll
        for (int k = 0; k < RPW; k++) {           // c = rows r0+1..r0+RPW
            load_row(r0 + 1 + k, c4, cm3, cp3);
            compute(1);
            rotate();
        }
    } else {
        // Chunk rows H-RPW..H-1. RPW-1 interior rows, then peel row H-1.
        float dm[3];
        load_row(r0 - 1, a4, dm, ap3);
        load_row(r0,     b4, bm3, bp3);
#pragma unroll
        for (int k = 0; k < RPW - 1; k++) {       // rows r0..H-2, c = rows r0+1..H-1
            load_row(r0 + 1 + k, c4, cm3, cp3);
            compute(1);
            rotate();
        }
        compute(2);                               // row H-1; stale c masked by mD=0
    }

    return acc;
}

__global__ __launch_bounds__(BLOCK_THREADS, 3)
void lap_kernel(const float* __restrict__ verts, float* __restrict__ out, float scale)
{
    const unsigned FULL = 0xFFFFFFFFu;
    int lane = threadIdx.x & 31;
    int gw   = (blockIdx.x * BLOCK_THREADS + threadIdx.x) >> 5;

    int bb  = gw / WPB;
    int rem = gw - bb * WPB;
    int cg  = rem % FCG;
    int rc  = rem / FCG;
    int r0  = rc * RPW;

    const float* vb = verts + (size_t)bb * NV * 3;
    int fidx  = cg * 32 + lane;          // float4 index within a grid row
    int fbase = cg * 128 + lane * 4;     // first float column owned by this lane
    bool doL = (lane == 0)  && (cg > 0);
    bool doR = (lane == 31) && (cg < FCG - 1);
    bool edge = (cg == 0) || (cg == FCG - 1);

    float acc;
    if (r0 == 0) {
        acc = edge ? walk<true, 0>(vb, fidx, lane, fbase, doL, doR, r0)
                   : walk<false,0>(vb, fidx, lane, fbase, doL, doR, r0);
    } else if (r0 + RPW == H) {
        acc = edge ? walk<true, 2>(vb, fidx, lane, fbase, doL, doR, r0)
                   : walk<false,2>(vb, fidx, lane, fbase, doL, doR, r0);
    } else {
        acc = edge ? walk<true, 1>(vb, fidx, lane, fbase, doL, doR, r0)
                   : walk<false,1>(vb, fidx, lane, fbase, doL, doR, r0);
    }

    // ---- reduce: warp -> block -> global atomic ----
#pragma unroll
    for (int off = 16; off > 0; off >>= 1)
        acc += __shfl_xor_sync(FULL, acc, off);

    __shared__ float warp_sums[WARPS_PER_BLOCK];
    int wid = threadIdx.x >> 5;
    if (lane == 0) warp_sums[wid] = acc;
    __syncthreads();

    if (threadIdx.x == 0) {
        float s = 0.0f;
#pragma unroll
        for (int k = 0; k < WARPS_PER_BLOCK; k++) s += warp_sums[k];
        atomicAdd(out, s * scale);
    }
}

extern "C" void kernel_launch(void* const* d_in, const int* in_sizes, int n_in,
                              void* d_out, int out_size) {
    const float* verts = (const float*)d_in[0];
    int B = in_sizes[0] / (NV * 3);

    float* out = (float*)d_out;
    zero_out_kernel<<<1, 32>>>(out);

    int total_warps  = B * WPB;                         // 24576
    int total_blocks = total_warps / WARPS_PER_BLOCK;   // 3072
    float scale = 1.0f / ((float)B * (float)NV);
    lap_kernel<<<total_blocks, BLOCK_THREADS>>>(verts, out, scale);
}